// round 8
// baseline (speedup 1.0000x reference)
#include <cuda_runtime.h>
#include <cuda_fp16.h>
#include <mma.h>
#include <cstdint>
#include <cstring>

using namespace nvcuda;

#define B_SZ   128
#define T_SZ   256
#define DIN    1024
#define UNITS  1024
#define NG     4096
#define NCLASS 1024

// ---------------- scratch ----------------
__device__ __half g_XPh[(size_t)B_SZ * T_SZ * NG];    // xp fp16, all timesteps
__device__ __half g_xh[(size_t)B_SZ * T_SZ * DIN];    // x in fp16
__device__ __half g_wkh[(size_t)DIN * NG];            // Wk in fp16
__device__ __half g_hT0[UNITS * B_SZ];                // transposed h fp16 ping
__device__ __half g_hT1[UNITS * B_SZ];                // transposed h fp16 pong
__device__ float  g_hrow[B_SZ * UNITS];               // final h fp32 row-major
__device__ float  g_cbuf[B_SZ * UNITS];               // final c fp32
__device__ volatile unsigned g_arrive[128];           // per-CTA step-completion flags

__device__ __forceinline__ float sigmf(float x) { return 1.f / (1.f + __expf(-x)); }

__device__ __forceinline__ uint32_t smem_u32(const void* p) {
    return (uint32_t)__cvta_generic_to_shared(p);
}
#define CP16(dst, src) asm volatile("cp.async.cg.shared.global [%0], [%1], 16;\n" :: "r"(dst), "l"(src))
#define CPC()  asm volatile("cp.async.commit_group;\n")
#define CPW1() asm volatile("cp.async.wait_group 1;\n")
#define CPW0() asm volatile("cp.async.wait_group 0;\n")

extern __shared__ float smem[];

// =====================================================================
// float -> half conversion
// =====================================================================
__global__ void f2h_kernel(const float* __restrict__ src, __half* __restrict__ dst, int n4)
{
    int i = blockIdx.x * blockDim.x + threadIdx.x;
    if (i < n4) {
        float4 v = *(const float4*)(src + (size_t)i * 4);
        __half2 a = __floats2half2_rn(v.x, v.y);
        __half2 b = __floats2half2_rn(v.z, v.w);
        uint2 pk;
        memcpy(&pk.x, &a, 4); memcpy(&pk.y, &b, 4);
        *(uint2*)(dst + (size_t)i * 4) = pk;
    }
}

// h0 -> transposed fp16: hT[u][b]
__global__ void h0_to_hT_kernel(const float* __restrict__ h0, __half* __restrict__ hT)
{
    int u = blockIdx.x;
    int b = threadIdx.x;
    hT[u * B_SZ + b] = __float2half(h0[(size_t)b * UNITS + u]);
}

// =====================================================================
// XP = X @ Wk : fp16 WMMA m16n16k16, 3-stage cp.async, fp16 OUTPUT.
// =====================================================================
#define XALD 72
#define XBLD 136
#define X_ABUF (128 * XALD)
#define X_BBUF (64 * XBLD)
#define XP_SMEM_BYTES (3 * (X_ABUF + X_BBUF) * 2)   // 107520 B >= staging 67584 B

__global__ __launch_bounds__(256) void xp_gemm_kernel(const __half* __restrict__ A,
                                                      const __half* __restrict__ Bm,
                                                      __half* __restrict__ C)
{
    __half* As = (__half*)smem;
    __half* Bs = As + 3 * X_ABUF;

    const int bm = blockIdx.y, bn = blockIdx.x;
    const int tid = threadIdx.x, wid = tid >> 5;
    const int wm = wid & 3, wn = wid >> 2;
    const __half* aBase = A + (size_t)(bm * 128) * DIN;
    const __half* bBase = Bm + bn * 128;

    wmma::fragment<wmma::accumulator, 16, 16, 16, float> acc[2][4];
#pragma unroll
    for (int i = 0; i < 2; i++)
#pragma unroll
        for (int j = 0; j < 4; j++) wmma::fill_fragment(acc[i][j], 0.0f);

    auto load_chunk = [&](int k, int s) {
        __half* ad = As + s * X_ABUF;
        const __half* asrc = aBase + k * 64;
#pragma unroll
        for (int i = 0; i < 4; i++) {
            int idx = tid + i * 256;
            int r = idx >> 3, c8 = idx & 7;
            CP16(smem_u32(ad + r * XALD + c8 * 8), asrc + (size_t)r * DIN + c8 * 8);
        }
        __half* bd = Bs + s * X_BBUF;
        const __half* bsrc = bBase + (size_t)(k * 64) * NG;
#pragma unroll
        for (int i = 0; i < 4; i++) {
            int idx = tid + i * 256;
            int r = idx >> 4, c8 = idx & 15;
            CP16(smem_u32(bd + r * XBLD + c8 * 8), bsrc + (size_t)r * NG + c8 * 8);
        }
        CPC();
    };

    load_chunk(0, 0);
    load_chunk(1, 1);

    for (int k = 0; k < 16; k++) {
        if (k < 15) { CPW1(); } else { CPW0(); }
        __syncthreads();
        if (k + 2 < 16) load_chunk(k + 2, (k + 2) % 3);

        const __half* ab = As + (k % 3) * X_ABUF;
        const __half* bb = Bs + (k % 3) * X_BBUF;
#pragma unroll
        for (int kk = 0; kk < 64; kk += 16) {
            wmma::fragment<wmma::matrix_a, 16, 16, 16, __half, wmma::row_major> af[2];
            wmma::fragment<wmma::matrix_b, 16, 16, 16, __half, wmma::row_major> bf[4];
#pragma unroll
            for (int i = 0; i < 2; i++)
                wmma::load_matrix_sync(af[i], ab + (wm * 32 + i * 16) * XALD + kk, XALD);
#pragma unroll
            for (int j = 0; j < 4; j++)
                wmma::load_matrix_sync(bf[j], bb + kk * XBLD + wn * 64 + j * 16, XBLD);
#pragma unroll
            for (int i = 0; i < 2; i++)
#pragma unroll
                for (int j = 0; j < 4; j++)
                    wmma::mma_sync(acc[i][j], af[i], bf[j], acc[i][j]);
        }
        __syncthreads();
    }

    // epilogue: stage fp32 in smem, write fp16 coalesced
    float* stg = (float*)smem;   // 128 x 132 floats = 67584 B
    __syncthreads();
#pragma unroll
    for (int i = 0; i < 2; i++)
#pragma unroll
        for (int j = 0; j < 4; j++)
            wmma::store_matrix_sync(stg + (wm * 32 + i * 16) * 132 + wn * 64 + j * 16,
                                    acc[i][j], 132, wmma::mem_row_major);
    __syncthreads();
#pragma unroll
    for (int m = 0; m < 8; m++) {
        int idx = tid + m * 256;          // 0..2047
        int row = idx >> 4, c8 = idx & 15;
        const float* s = stg + row * 132 + c8 * 8;
        uint4 o;
        __half2 h0 = __floats2half2_rn(s[0], s[1]);
        __half2 h1 = __floats2half2_rn(s[2], s[3]);
        __half2 h2 = __floats2half2_rn(s[4], s[5]);
        __half2 h3 = __floats2half2_rn(s[6], s[7]);
        memcpy(&o.x, &h0, 4); memcpy(&o.y, &h1, 4);
        memcpy(&o.z, &h2, 4); memcpy(&o.w, &h3, 4);
        *(uint4*)(C + (size_t)(bm * 128 + row) * NG + bn * 128 + c8 * 8) = o;
    }
}

// =====================================================================
// Persistent recurrence, fp16 WMMA, KC=64, per-producer dataflow flags.
// 128 CTAs x 256 threads. CTA: units [u0,u0+8) => 32 gate-cols, M=128, K=1024.
// Chunk kc (64 units) produced by CTAs kc*8..kc*8+7; consumer warp w loads
// the 8 rows produced by CTA kc*8+w and spins on that single flag.
// =====================================================================
#define WSLD 40                          // halfs: 32 + 8
#define HLD  136                         // halfs: 128 + 8
#define XLD  40                          // halfs: 32 + 8 (80 B, 16B-aligned rows)
#define KC   64
#define NCH  (UNITS / KC)                // 16

#define WS_HALFS (UNITS * WSLD)          // 40960 halfs = 80 KB
#define HS_STG   (KC * HLD)              // 8704 halfs
#define HS_HALFS (3 * HS_STG)            // 26112
#define XS_HALFS (B_SZ * XLD)            // 5120
#define P_FLTS   (5 * 32)

#define OFF_HS_H WS_HALFS
#define OFF_XS_H (OFF_HS_H + HS_HALFS)                 // 67072 (x2 = 134144 B, 16B-aligned)
#define OFF_P_F  ((OFF_XS_H + XS_HALFS) / 2)           // float idx 36096
#define PERS_SMEM_BYTES ((OFF_P_F + P_FLTS) * 4)       // 145024

__global__ __launch_bounds__(256, 1) void persistent_lstm_kernel(
    const float* __restrict__ Wr,
    const float* __restrict__ br,
    const float* __restrict__ bk,
    const float* __restrict__ alpha,
    const float* __restrict__ beta1,
    const float* __restrict__ beta2,
    const float* __restrict__ c0)
{
    __half* Ws = (__half*)smem;
    __half* Hs = Ws + OFF_HS_H;
    __half* Xsh = Ws + OFF_XS_H;
    float* Pbk = smem + OFF_P_F;
    float* Pbr = Pbk + 32;
    float* Pal = Pbr + 32;
    float* Pb1 = Pal + 32;
    float* Pb2 = Pb1 + 32;

    const int tid = threadIdx.x;
    const int wid = tid >> 5;
    const int lane = tid & 31;
    const int wm = wid & 3;      // 4 warps over M: 32 rows each
    const int wn = wid >> 2;     // 2 warps over N: 16 cols each
    const int u0 = blockIdx.x * 8;

    // ---- prologue: Wr slice -> smem fp16, [k][n] ld 40 ----
    for (int it = 0; it < 128; it++) {
        int idx = tid + it * 256;
        int n = idx & 31, k = idx >> 5;
        Ws[k * WSLD + n] = __float2half(Wr[(size_t)k * NG + (n >> 3) * UNITS + u0 + (n & 7)]);
    }
    if (tid < 32) {
        int jj = (tid >> 3) * UNITS + u0 + (tid & 7);
        Pbk[tid] = bk[jj]; Pbr[tid] = br[jj];
        Pal[tid] = alpha[jj]; Pb1[tid] = beta1[jj]; Pb2[tid] = beta2[jj];
    }
    const int cu = tid >> 5;           // unit 0..7
    const int cb0 = (tid & 31) * 4;    // batch rows cb0..cb0+3
    float creg[4];
#pragma unroll
    for (int i = 0; i < 4; i++)
        creg[i] = c0[(size_t)(cb0 + i) * UNITS + u0 + cu];
    __syncthreads();

    // ---- time loop ----
    for (int t = 0; t < T_SZ; t++) {
        const __half* hT = (t & 1) ? g_hT1 : g_hT0;
        __half* hTn = (t & 1) ? g_hT0 : g_hT1;

        wmma::fragment<wmma::accumulator, 16, 16, 16, float> acc[2];
        wmma::fill_fragment(acc[0], 0.0f);
        wmma::fill_fragment(acc[1], 0.0f);

        auto load_chunk = [&](int kc, int s) {
            // warp w depends only on producer CTA kc*8+w having finished step t-1
            if (t > 0) {
                volatile unsigned* f = &g_arrive[kc * 8 + wid];
                while (*f < (unsigned)t) __nanosleep(20);
                __threadfence();
            }
            __half* hd = Hs + s * HS_STG;
            const __half* hsrc = hT + kc * KC * B_SZ;
            int r0 = wid * 8;
#pragma unroll
            for (int m = 0; m < 4; m++) {
                int lin = m * 32 + lane;      // 0..127
                int r = r0 + (lin >> 4);
                int c16 = lin & 15;
                CP16(smem_u32(hd + r * HLD + c16 * 8), hsrc + (size_t)r * B_SZ + c16 * 8);
            }
            if (kc == 0) {
                // xp fp16 tile [128 b][32 gc] rides with chunk 0 (XLD=40: 16B-aligned rows)
#pragma unroll
                for (int j = 0; j < 2; j++) {
                    int i = tid + j * 256;    // 0..511
                    int b = i >> 2, g = i & 3;
                    CP16(smem_u32(Xsh + b * XLD + g * 8),
                         g_XPh + ((size_t)b * T_SZ + t) * NG + g * UNITS + u0);
                }
            }
            CPC();
        };

        load_chunk(0, 0);
        load_chunk(1, 1);

        for (int kc = 0; kc < NCH; kc++) {
            if (kc < NCH - 1) { CPW1(); } else { CPW0(); }
            __syncthreads();
            if (kc + 2 < NCH) load_chunk(kc + 2, (kc + 2) % 3);

            const __half* hb = Hs + (kc % 3) * HS_STG;
            const __half* wb = Ws + kc * KC * WSLD;
#pragma unroll
            for (int kk = 0; kk < KC; kk += 16) {
                wmma::fragment<wmma::matrix_a, 16, 16, 16, __half, wmma::col_major> af[2];
                wmma::fragment<wmma::matrix_b, 16, 16, 16, __half, wmma::row_major> bf;
                wmma::load_matrix_sync(af[0], hb + kk * HLD + wm * 32, HLD);
                wmma::load_matrix_sync(af[1], hb + kk * HLD + wm * 32 + 16, HLD);
                wmma::load_matrix_sync(bf, wb + kk * WSLD + wn * 16, WSLD);
                wmma::mma_sync(acc[0], af[0], bf, acc[0]);
                wmma::mma_sync(acc[1], af[1], bf, acc[1]);
            }
        }
        __syncthreads();   // Hs free

        // dump hp tile [128][32] -> Zs (reuse Hs), ld 36 floats
        float* Zs = (float*)Hs;
        wmma::store_matrix_sync(Zs + (wm * 32) * 36 + wn * 16, acc[0], 36, wmma::mem_row_major);
        wmma::store_matrix_sync(Zs + (wm * 32 + 16) * 36 + wn * 16, acc[1], 36, wmma::mem_row_major);
        __syncthreads();

        // pointwise: thread owns u=cu, b=cb0..cb0+3
        float hout[4];
#pragma unroll
        for (int i = 0; i < 4; i++) {
            int b = cb0 + i;
            float z[4];
#pragma unroll
            for (int g = 0; g < 4; g++) {
                int cc = g * 8 + cu;
                float hp = Zs[b * 36 + cc] + Pbr[cc];
                float xv = __half2float(Xsh[b * XLD + cc]) + Pbk[cc];
                z[g] = Pal[cc] * xv * hp + Pb1[cc] * xv + Pb2[cc] * hp;
            }
            float cn = tanhf(z[2]) * sigmf(z[0]) + creg[i] * sigmf(z[1]);
            float hn = tanhf(cn) * sigmf(z[3]);
            creg[i] = cn;
            hout[i] = hn;
        }
        __half2 p0 = __floats2half2_rn(hout[0], hout[1]);
        __half2 p1 = __floats2half2_rn(hout[2], hout[3]);
        uint2 pk;
        memcpy(&pk.x, &p0, 4); memcpy(&pk.y, &p1, 4);
        *(uint2*)(hTn + (u0 + cu) * B_SZ + cb0) = pk;

        if (t == T_SZ - 1) {
#pragma unroll
            for (int i = 0; i < 4; i++) {
                g_hrow[(size_t)(cb0 + i) * UNITS + u0 + cu] = hout[i];
                g_cbuf[(size_t)(cb0 + i) * UNITS + u0 + cu] = creg[i];
            }
        }

        // publish: this CTA finished step t (h(t+1) rows written)
        __threadfence();
        __syncthreads();
        if (tid == 0) g_arrive[blockIdx.x] = (unsigned)(t + 1);
    }
}

// =====================================================================
// classifier: out = h @ Wc + bc (fp32, exact)
// =====================================================================
__global__ void classify_kernel(const float* __restrict__ h,
                                const float* __restrict__ Wc,
                                const float* __restrict__ bc,
                                float* __restrict__ out)
{
    int col = blockIdx.x * 256 + threadIdx.x;
    int b = blockIdx.y;
    const float* hr = &h[(size_t)b * UNITS];
    float s = 0.f;
#pragma unroll 8
    for (int k = 0; k < UNITS; k++)
        s += hr[k] * Wc[(size_t)k * NCLASS + col];
    out[(size_t)b * NCLASS + col] = s + bc[col];
}

// =====================================================================
// launch
// =====================================================================
extern "C" void kernel_launch(void* const* d_in, const int* in_sizes, int n_in,
                              void* d_out, int out_size)
{
    const float* x     = (const float*)d_in[0];
    const float* h0    = (const float*)d_in[1];
    const float* c0    = (const float*)d_in[2];
    const float* Wk    = (const float*)d_in[3];
    const float* bk    = (const float*)d_in[4];
    const float* Wr    = (const float*)d_in[5];
    const float* br    = (const float*)d_in[6];
    const float* alpha = (const float*)d_in[7];
    const float* beta1 = (const float*)d_in[8];
    const float* beta2 = (const float*)d_in[9];
    const float* Wc    = (const float*)d_in[10];
    const float* bc    = (const float*)d_in[11];
    float* out = (float*)d_out;

    float *pHrow, *pC;
    __half *pXPh, *pXH, *pWKH, *pHT0;
    cudaGetSymbolAddress((void**)&pXPh, g_XPh);
    cudaGetSymbolAddress((void**)&pXH, g_xh);
    cudaGetSymbolAddress((void**)&pWKH, g_wkh);
    cudaGetSymbolAddress((void**)&pHT0, g_hT0);
    cudaGetSymbolAddress((void**)&pHrow, g_hrow);
    cudaGetSymbolAddress((void**)&pC, g_cbuf);
    void *pArr;
    cudaGetSymbolAddress(&pArr, (const void*)g_arrive);

    cudaFuncSetAttribute(xp_gemm_kernel, cudaFuncAttributeMaxDynamicSharedMemorySize, XP_SMEM_BYTES);
    cudaFuncSetAttribute(persistent_lstm_kernel, cudaFuncAttributeMaxDynamicSharedMemorySize, PERS_SMEM_BYTES);

    cudaMemsetAsync(pArr, 0, 128 * sizeof(unsigned));

    f2h_kernel<<<(B_SZ * T_SZ * DIN / 4 + 255) / 256, 256>>>(x, pXH, B_SZ * T_SZ * DIN / 4);
    f2h_kernel<<<(DIN * NG / 4 + 255) / 256, 256>>>(Wk, pWKH, DIN * NG / 4);
    h0_to_hT_kernel<<<UNITS, B_SZ>>>(h0, pHT0);

    xp_gemm_kernel<<<dim3(NG / 128, (B_SZ * T_SZ) / 128), 256, XP_SMEM_BYTES>>>(pXH, pWKH, pXPh);

    persistent_lstm_kernel<<<UNITS / 8, 256, PERS_SMEM_BYTES>>>(
        Wr, br, bk, alpha, beta1, beta2, c0);

    classify_kernel<<<dim3(NCLASS / 256, B_SZ), 256>>>(pHrow, Wc, bc, out);

    const size_t stateBytes = (size_t)B_SZ * UNITS * sizeof(float);
    cudaMemcpyAsync(out + (size_t)B_SZ * NCLASS, pHrow, stateBytes, cudaMemcpyDeviceToDevice);
    cudaMemcpyAsync(out + (size_t)B_SZ * NCLASS + (size_t)B_SZ * UNITS, pC, stateBytes,
                    cudaMemcpyDeviceToDevice);
}

// round 9
// speedup vs baseline: 2.3558x; 2.3558x over previous
#include <cuda_runtime.h>
#include <cuda_fp16.h>
#include <mma.h>
#include <cstdint>
#include <cstring>

using namespace nvcuda;

#define B_SZ   128
#define T_SZ   256
#define DIN    1024
#define UNITS  1024
#define NG     4096
#define NCLASS 1024

// ---------------- scratch ----------------
__device__ float  g_XP[(size_t)B_SZ * T_SZ * NG];     // xp fp32, all timesteps
__device__ __half g_xh[(size_t)B_SZ * T_SZ * DIN];    // x in fp16
__device__ __half g_wkh[(size_t)DIN * NG];            // Wk in fp16
__device__ __half g_hT0[UNITS * B_SZ];                // transposed h fp16 ping
__device__ __half g_hT1[UNITS * B_SZ];                // transposed h fp16 pong
__device__ float  g_hrow[B_SZ * UNITS];               // final h fp32 row-major
__device__ float  g_cbuf[B_SZ * UNITS];               // final c fp32
__device__ unsigned g_bar_count;
__device__ unsigned g_bar_epoch;

__device__ __forceinline__ float sigmf(float x) { return 1.f / (1.f + __expf(-x)); }

__device__ __forceinline__ uint32_t smem_u32(const void* p) {
    return (uint32_t)__cvta_generic_to_shared(p);
}
#define CP16(dst, src) asm volatile("cp.async.cg.shared.global [%0], [%1], 16;\n" :: "r"(dst), "l"(src))
#define CPC()  asm volatile("cp.async.commit_group;\n")
#define CPW1() asm volatile("cp.async.wait_group 1;\n")
#define CPW0() asm volatile("cp.async.wait_group 0;\n")

extern __shared__ float smem[];

// =====================================================================
// float -> half conversion
// =====================================================================
__global__ void f2h_kernel(const float* __restrict__ src, __half* __restrict__ dst, int n4)
{
    int i = blockIdx.x * blockDim.x + threadIdx.x;
    if (i < n4) {
        float4 v = *(const float4*)(src + (size_t)i * 4);
        __half2 a = __floats2half2_rn(v.x, v.y);
        __half2 b = __floats2half2_rn(v.z, v.w);
        uint2 pk;
        memcpy(&pk.x, &a, 4); memcpy(&pk.y, &b, 4);
        *(uint2*)(dst + (size_t)i * 4) = pk;
    }
}

// h0 -> transposed fp16: hT[u][b]
__global__ void h0_to_hT_kernel(const float* __restrict__ h0, __half* __restrict__ hT)
{
    int u = blockIdx.x;
    int b = threadIdx.x;
    hT[u * B_SZ + b] = __float2half(h0[(size_t)b * UNITS + u]);
}

// =====================================================================
// XP = X @ Wk : fp16 WMMA m16n16k16, 3-stage cp.async, fp32 output (R5)
// =====================================================================
#define XALD 72
#define XBLD 136
#define X_ABUF (128 * XALD)
#define X_BBUF (64 * XBLD)
#define XP_SMEM_BYTES (3 * (X_ABUF + X_BBUF) * 2)

__global__ __launch_bounds__(256) void xp_gemm_kernel(const __half* __restrict__ A,
                                                      const __half* __restrict__ Bm,
                                                      float* __restrict__ C)
{
    __half* As = (__half*)smem;
    __half* Bs = As + 3 * X_ABUF;

    const int bm = blockIdx.y, bn = blockIdx.x;
    const int tid = threadIdx.x, wid = tid >> 5;
    const int wm = wid & 3, wn = wid >> 2;
    const __half* aBase = A + (size_t)(bm * 128) * DIN;
    const __half* bBase = Bm + bn * 128;

    wmma::fragment<wmma::accumulator, 16, 16, 16, float> acc[2][4];
#pragma unroll
    for (int i = 0; i < 2; i++)
#pragma unroll
        for (int j = 0; j < 4; j++) wmma::fill_fragment(acc[i][j], 0.0f);

    auto load_chunk = [&](int k, int s) {
        __half* ad = As + s * X_ABUF;
        const __half* asrc = aBase + k * 64;
#pragma unroll
        for (int i = 0; i < 4; i++) {
            int idx = tid + i * 256;
            int r = idx >> 3, c8 = idx & 7;
            CP16(smem_u32(ad + r * XALD + c8 * 8), asrc + (size_t)r * DIN + c8 * 8);
        }
        __half* bd = Bs + s * X_BBUF;
        const __half* bsrc = bBase + (size_t)(k * 64) * NG;
#pragma unroll
        for (int i = 0; i < 4; i++) {
            int idx = tid + i * 256;
            int r = idx >> 4, c8 = idx & 15;
            CP16(smem_u32(bd + r * XBLD + c8 * 8), bsrc + (size_t)r * NG + c8 * 8);
        }
        CPC();
    };

    load_chunk(0, 0);
    load_chunk(1, 1);

    for (int k = 0; k < 16; k++) {
        if (k < 15) { CPW1(); } else { CPW0(); }
        __syncthreads();
        if (k + 2 < 16) load_chunk(k + 2, (k + 2) % 3);

        const __half* ab = As + (k % 3) * X_ABUF;
        const __half* bb = Bs + (k % 3) * X_BBUF;
#pragma unroll
        for (int kk = 0; kk < 64; kk += 16) {
            wmma::fragment<wmma::matrix_a, 16, 16, 16, __half, wmma::row_major> af[2];
            wmma::fragment<wmma::matrix_b, 16, 16, 16, __half, wmma::row_major> bf[4];
#pragma unroll
            for (int i = 0; i < 2; i++)
                wmma::load_matrix_sync(af[i], ab + (wm * 32 + i * 16) * XALD + kk, XALD);
#pragma unroll
            for (int j = 0; j < 4; j++)
                wmma::load_matrix_sync(bf[j], bb + kk * XBLD + wn * 64 + j * 16, XBLD);
#pragma unroll
            for (int i = 0; i < 2; i++)
#pragma unroll
                for (int j = 0; j < 4; j++)
                    wmma::mma_sync(acc[i][j], af[i], bf[j], acc[i][j]);
        }
        __syncthreads();
    }

#pragma unroll
    for (int i = 0; i < 2; i++)
#pragma unroll
        for (int j = 0; j < 4; j++) {
            size_t row = (size_t)(bm * 128 + wm * 32 + i * 16);
            size_t col = (size_t)(bn * 128 + wn * 64 + j * 16);
            wmma::store_matrix_sync(&C[row * NG + col], acc[i][j], NG, wmma::mem_row_major);
        }
}

// =====================================================================
// Persistent recurrence, fp16 WMMA, KC=64, atomic barrier (R5 base),
// coalesced Xs smem staging for XP (fp32, stride 36 floats = 144 B).
// 128 CTAs x 256 threads. CTA: units [u0,u0+8) => 32 gate-cols, M=128, K=1024.
// =====================================================================
#define WSLD 40                          // halfs: 32 + 8
#define HLD  136                         // halfs: 128 + 8
#define KC   64
#define NCH  (UNITS / KC)                // 16

#define WS_HALFS (UNITS * WSLD)          // 40960 halfs = 80 KB
#define HS_STG   (KC * HLD)              // 8704 halfs
#define HS_HALFS (3 * HS_STG)            // 26112 halfs
#define XS_FLTS  (B_SZ * 36)             // 4608 floats
#define P_FLTS   (5 * 32)

#define OFF_HS_H WS_HALFS
#define OFF_XS_F ((OFF_HS_H + HS_HALFS) / 2)           // float idx 33536 (byte 134144, 16B-aligned)
#define OFF_P_F  (OFF_XS_F + XS_FLTS)
#define PERS_SMEM_BYTES ((OFF_P_F + P_FLTS) * 4)       // 153216

__global__ __launch_bounds__(256, 1) void persistent_lstm_kernel(
    const float* __restrict__ Wr,
    const float* __restrict__ br,
    const float* __restrict__ bk,
    const float* __restrict__ alpha,
    const float* __restrict__ beta1,
    const float* __restrict__ beta2,
    const float* __restrict__ c0)
{
    __half* Ws = (__half*)smem;
    __half* Hs = Ws + OFF_HS_H;
    float* Xs  = smem + OFF_XS_F;
    float* Pbk = smem + OFF_P_F;
    float* Pbr = Pbk + 32;
    float* Pal = Pbr + 32;
    float* Pb1 = Pal + 32;
    float* Pb2 = Pb1 + 32;

    const int tid = threadIdx.x;
    const int wid = tid >> 5;
    const int wm = wid & 3;      // 4 warps over M: 32 rows each
    const int wn = wid >> 2;     // 2 warps over N: 16 cols each
    const int u0 = blockIdx.x * 8;

    // ---- prologue: Wr slice -> smem fp16, [k][n] ld 40 ----
    for (int it = 0; it < 128; it++) {
        int idx = tid + it * 256;
        int n = idx & 31, k = idx >> 5;
        Ws[k * WSLD + n] = __float2half(Wr[(size_t)k * NG + (n >> 3) * UNITS + u0 + (n & 7)]);
    }
    if (tid < 32) {
        int jj = (tid >> 3) * UNITS + u0 + (tid & 7);
        Pbk[tid] = bk[jj]; Pbr[tid] = br[jj];
        Pal[tid] = alpha[jj]; Pb1[tid] = beta1[jj]; Pb2[tid] = beta2[jj];
    }
    const int cu = tid >> 5;           // unit 0..7
    const int cb0 = (tid & 31) * 4;    // batch rows cb0..cb0+3
    float creg[4];
#pragma unroll
    for (int i = 0; i < 4; i++)
        creg[i] = c0[(size_t)(cb0 + i) * UNITS + u0 + cu];
    __syncthreads();

    // ---- time loop ----
    for (int t = 0; t < T_SZ; t++) {
        const __half* hT = (t & 1) ? g_hT1 : g_hT0;
        __half* hTn = (t & 1) ? g_hT0 : g_hT1;

        wmma::fragment<wmma::accumulator, 16, 16, 16, float> acc[2];
        wmma::fill_fragment(acc[0], 0.0f);
        wmma::fill_fragment(acc[1], 0.0f);

        auto load_chunk = [&](int kc, int s) {
            __half* hd = Hs + s * HS_STG;
            const __half* hsrc = hT + kc * KC * B_SZ;
#pragma unroll
            for (int j = 0; j < 4; j++) {
                int i = tid + j * 256;        // 1024 x 16B
                int kr = i >> 4, b8 = (i & 15) * 8;
                CP16(smem_u32(hd + kr * HLD + b8), hsrc + kr * B_SZ + b8);
            }
            if (kc == 0) {
                // xp fp32 tile [128 b][32 gc] rides with chunk 0 (coalesced 16B, stride 144B)
#pragma unroll
                for (int j = 0; j < 4; j++) {
                    int i = tid + j * 256;    // 1024 x 16B
                    int b = i >> 3, q = i & 7;
                    int g = q >> 1, part = q & 1;
                    CP16(smem_u32(Xs + b * 36 + g * 8 + part * 4),
                         g_XP + ((size_t)b * T_SZ + t) * NG + g * UNITS + u0 + part * 4);
                }
            }
            CPC();
        };

        load_chunk(0, 0);
        load_chunk(1, 1);

        for (int kc = 0; kc < NCH; kc++) {
            if (kc < NCH - 1) { CPW1(); } else { CPW0(); }
            __syncthreads();
            if (kc + 2 < NCH) load_chunk(kc + 2, (kc + 2) % 3);

            const __half* hb = Hs + (kc % 3) * HS_STG;
            const __half* wb = Ws + kc * KC * WSLD;
#pragma unroll
            for (int kk = 0; kk < KC; kk += 16) {
                wmma::fragment<wmma::matrix_a, 16, 16, 16, __half, wmma::col_major> af[2];
                wmma::fragment<wmma::matrix_b, 16, 16, 16, __half, wmma::row_major> bf;
                wmma::load_matrix_sync(af[0], hb + kk * HLD + wm * 32, HLD);
                wmma::load_matrix_sync(af[1], hb + kk * HLD + wm * 32 + 16, HLD);
                wmma::load_matrix_sync(bf, wb + kk * WSLD + wn * 16, WSLD);
                wmma::mma_sync(acc[0], af[0], bf, acc[0]);
                wmma::mma_sync(acc[1], af[1], bf, acc[1]);
            }
        }
        __syncthreads();   // Hs free

        // dump hp tile [128][32] -> Zs (reuse Hs), ld 36 floats
        float* Zs = (float*)Hs;
        wmma::store_matrix_sync(Zs + (wm * 32) * 36 + wn * 16, acc[0], 36, wmma::mem_row_major);
        wmma::store_matrix_sync(Zs + (wm * 32 + 16) * 36 + wn * 16, acc[1], 36, wmma::mem_row_major);
        __syncthreads();

        // pointwise: thread owns u=cu, b=cb0..cb0+3
        float hout[4];
#pragma unroll
        for (int i = 0; i < 4; i++) {
            int b = cb0 + i;
            float z[4];
#pragma unroll
            for (int g = 0; g < 4; g++) {
                int cc = g * 8 + cu;
                float hp = Zs[b * 36 + cc] + Pbr[cc];
                float xv = Xs[b * 36 + cc] + Pbk[cc];
                z[g] = Pal[cc] * xv * hp + Pb1[cc] * xv + Pb2[cc] * hp;
            }
            float cn = tanhf(z[2]) * sigmf(z[0]) + creg[i] * sigmf(z[1]);
            float hn = tanhf(cn) * sigmf(z[3]);
            creg[i] = cn;
            hout[i] = hn;
        }
        __half2 p0 = __floats2half2_rn(hout[0], hout[1]);
        __half2 p1 = __floats2half2_rn(hout[2], hout[3]);
        uint2 pk;
        memcpy(&pk.x, &p0, 4); memcpy(&pk.y, &p1, 4);
        *(uint2*)(hTn + (u0 + cu) * B_SZ + cb0) = pk;

        if (t == T_SZ - 1) {
#pragma unroll
            for (int i = 0; i < 4; i++) {
                g_hrow[(size_t)(cb0 + i) * UNITS + u0 + cu] = hout[i];
                g_cbuf[(size_t)(cb0 + i) * UNITS + u0 + cu] = creg[i];
            }
        }

        // ---- grid barrier (R5: atomic count + epoch release) ----
        __threadfence();
        __syncthreads();
        if (tid == 0) {
            unsigned arr = atomicAdd(&g_bar_count, 1u);
            if (arr == gridDim.x - 1) {
                atomicExch(&g_bar_count, 0u);
                __threadfence();
                atomicAdd(&g_bar_epoch, 1u);
            } else {
                volatile unsigned* ep = &g_bar_epoch;
                while (*ep < (unsigned)(t + 1)) __nanosleep(64);
            }
        }
        __syncthreads();
    }
}

// =====================================================================
// classifier: out = h @ Wc + bc (fp32, exact)
// =====================================================================
__global__ void classify_kernel(const float* __restrict__ h,
                                const float* __restrict__ Wc,
                                const float* __restrict__ bc,
                                float* __restrict__ out)
{
    int col = blockIdx.x * 256 + threadIdx.x;
    int b = blockIdx.y;
    const float* hr = &h[(size_t)b * UNITS];
    float s = 0.f;
#pragma unroll 8
    for (int k = 0; k < UNITS; k++)
        s += hr[k] * Wc[(size_t)k * NCLASS + col];
    out[(size_t)b * NCLASS + col] = s + bc[col];
}

// =====================================================================
// launch
// =====================================================================
extern "C" void kernel_launch(void* const* d_in, const int* in_sizes, int n_in,
                              void* d_out, int out_size)
{
    const float* x     = (const float*)d_in[0];
    const float* h0    = (const float*)d_in[1];
    const float* c0    = (const float*)d_in[2];
    const float* Wk    = (const float*)d_in[3];
    const float* bk    = (const float*)d_in[4];
    const float* Wr    = (const float*)d_in[5];
    const float* br    = (const float*)d_in[6];
    const float* alpha = (const float*)d_in[7];
    const float* beta1 = (const float*)d_in[8];
    const float* beta2 = (const float*)d_in[9];
    const float* Wc    = (const float*)d_in[10];
    const float* bc    = (const float*)d_in[11];
    float* out = (float*)d_out;

    float *pXP, *pHrow, *pC;
    __half *pXH, *pWKH, *pHT0;
    cudaGetSymbolAddress((void**)&pXP, g_XP);
    cudaGetSymbolAddress((void**)&pXH, g_xh);
    cudaGetSymbolAddress((void**)&pWKH, g_wkh);
    cudaGetSymbolAddress((void**)&pHT0, g_hT0);
    cudaGetSymbolAddress((void**)&pHrow, g_hrow);
    cudaGetSymbolAddress((void**)&pC, g_cbuf);
    unsigned *pCnt, *pEp;
    cudaGetSymbolAddress((void**)&pCnt, g_bar_count);
    cudaGetSymbolAddress((void**)&pEp, g_bar_epoch);

    cudaFuncSetAttribute(xp_gemm_kernel, cudaFuncAttributeMaxDynamicSharedMemorySize, XP_SMEM_BYTES);
    cudaFuncSetAttribute(persistent_lstm_kernel, cudaFuncAttributeMaxDynamicSharedMemorySize, PERS_SMEM_BYTES);

    cudaMemsetAsync(pCnt, 0, sizeof(unsigned));
    cudaMemsetAsync(pEp, 0, sizeof(unsigned));

    f2h_kernel<<<(B_SZ * T_SZ * DIN / 4 + 255) / 256, 256>>>(x, pXH, B_SZ * T_SZ * DIN / 4);
    f2h_kernel<<<(DIN * NG / 4 + 255) / 256, 256>>>(Wk, pWKH, DIN * NG / 4);
    h0_to_hT_kernel<<<UNITS, B_SZ>>>(h0, pHT0);

    xp_gemm_kernel<<<dim3(NG / 128, (B_SZ * T_SZ) / 128), 256, XP_SMEM_BYTES>>>(pXH, pWKH, pXP);

    persistent_lstm_kernel<<<UNITS / 8, 256, PERS_SMEM_BYTES>>>(
        Wr, br, bk, alpha, beta1, beta2, c0);

    classify_kernel<<<dim3(NCLASS / 256, B_SZ), 256>>>(pHrow, Wc, bc, out);

    const size_t stateBytes = (size_t)B_SZ * UNITS * sizeof(float);
    cudaMemcpyAsync(out + (size_t)B_SZ * NCLASS, pHrow, stateBytes, cudaMemcpyDeviceToDevice);
    cudaMemcpyAsync(out + (size_t)B_SZ * NCLASS + (size_t)B_SZ * UNITS, pC, stateBytes,
                    cudaMemcpyDeviceToDevice);
}